// round 12
// baseline (speedup 1.0000x reference)
#include <cuda_runtime.h>
#include <cuda_fp16.h>
#include <cstdint>

// LSTMClassifier B=2048,T=256,F=64,H=128 via mma.sync (HMMA) on sm_103.
// K1 prepack: Wih/Whh fp32 -> fp16 A-fragments in global, frag-register order.
// K2 fused:   32 supersteps x (phase A: gx[8] = W_ih x + bias into SMEM;
//             8 recurrence steps: D = gx[tl] (same-thread LDS) + W_hh h).
//             h stored [row][unit] chunk-swizzled, non-trans ldmatrix B;
//             f16x2 activations + packed butterfly; 10 barriers / 8 steps.

#define T_STEPS 256
#define NTHREADS 512
#define NBLOCKS 128

__device__ uint4 g_whh_f[8192];       // [32 mt][8 kt][32 lane] A-frags
__device__ uint4 g_wih_f[4096];       // [32 mt][4 kt][32 lane] A-frags

__device__ __forceinline__ uint32_t smem_u32(const void* p) {
    uint32_t a;
    asm("{ .reg .u64 t; cvta.to.shared.u64 t, %1; cvt.u32.u64 %0, t; }" : "=r"(a) : "l"(p));
    return a;
}
__device__ __forceinline__ uint32_t f2h2(float a, float b) {
    __half2 h = __floats2half2_rn(a, b);
    return *(uint32_t*)&h;
}
__device__ __forceinline__ uint32_t tanh2(uint32_t x) {
    uint32_t r;
    asm("tanh.approx.f16x2 %0, %1;" : "=r"(r) : "r"(x));
    return r;
}

#define LDSM_X4(r0, r1, r2, r3, a) \
    asm volatile("ldmatrix.sync.aligned.m8n8.x4.shared.b16 {%0,%1,%2,%3}, [%4];" \
                 : "=r"(r0), "=r"(r1), "=r"(r2), "=r"(r3) : "r"(a))

#define MMA16816(d, a0, a1, a2, a3, b0, b1) \
    asm volatile("mma.sync.aligned.m16n8k16.row.col.f32.f16.f16.f32 " \
                 "{%0,%1,%2,%3}, {%4,%5,%6,%7}, {%8,%9}, {%0,%1,%2,%3};" \
                 : "+f"((d)[0]), "+f"((d)[1]), "+f"((d)[2]), "+f"((d)[3]) \
                 : "r"(a0), "r"(a1), "r"(a2), "r"(a3), "r"(b0), "r"(b1))

__device__ __forceinline__ float sigm_exact(float v) {
    float e = __expf(-v);
    return __fdividef(1.0f, 1.0f + e);
}

// ===================== K1: prepack weights into fragment order ==============
__global__ void prepack_kernel(const float* __restrict__ Wih,
                               const float* __restrict__ Whh) {
    int idx = blockIdx.x * blockDim.x + threadIdx.x;   // 0..12287
    int isIh = idx >= 8192;
    int id = isIh ? idx - 8192 : idx;
    int lane = id & 31;
    int ktc = isIh ? 4 : 8;
    int kt = (id >> 5) % ktc;
    int mt = (id >> 5) / ktc;
    if (mt >= 32) return;
    int g = lane >> 2, cq = lane & 3;
    uint32_t u[4];
#pragma unroll
    for (int i = 0; i < 4; i++) {
        int j  = g + (i & 1) * 8;
        int kl = 2 * cq + (i >> 1) * 8;
        int pr = mt * 16 + j;
        int uu = pr >> 2, q = pr & 3;
        int row = q * 128 + uu;
        float2 v;
        if (isIh) v = *(const float2*)(Wih + row * 64 + kt * 16 + kl);
        else      v = *(const float2*)(Whh + row * 128 + kt * 16 + kl);
        u[i] = f2h2(v.x, v.y);
    }
    uint4 val = make_uint4(u[0], u[1], u[2], u[3]);
    if (isIh) g_wih_f[(mt * 4 + kt) * 32 + lane] = val;
    else      g_whh_f[(mt * 8 + kt) * 32 + lane] = val;
}

// ===================== K2: fused prepass + recurrence =======================
// smem: gx 128KB [8 tl][2 j][512 tid][16B] | x stage 16KB [8 tl][16 r][128B]
//       | h dbuf 2x4KB.  Head overlays the gx region after/near loop end.
#define GX_OFF  0
#define XB_OFF  131072
#define HB_OFF  147456
#define SMEM_TOTAL 155648
#define HS_OFF  0                     // overlays gx tl=0 slot (safe, see text)
#define W1T_OFF 16384
#define ZS_OFF  32768

__global__ __launch_bounds__(NTHREADS, 1) void lstm_fused_kernel(
    const float* __restrict__ x,
    const float* __restrict__ bih, const float* __restrict__ bhh,
    const float* __restrict__ W1, const float* __restrict__ b1,
    const float* __restrict__ W2, const float* __restrict__ b2,
    float* __restrict__ out)
{
    extern __shared__ char smem[];
    const uint32_t sb = smem_u32(smem);
    const int tid  = threadIdx.x;
    const int wid  = tid >> 5;
    const int lane = tid & 31;
    const int b0   = blockIdx.x * 16;

    // zero h buffer 0 (h0 = 0)
    for (int i = tid; i < 1024; i += NTHREADS)
        ((uint32_t*)(smem + HB_OFF))[i] = 0;

    // W_hh A-frags register-resident
    uint32_t ah[2][8][4];
#pragma unroll
    for (int mt = 0; mt < 2; mt++)
#pragma unroll
        for (int kt = 0; kt < 8; kt++) {
            uint4 a = g_whh_f[((wid * 2 + mt) * 8 + kt) * 32 + lane];
            ah[mt][kt][0] = a.x; ah[mt][kt][1] = a.y;
            ah[mt][kt][2] = a.z; ah[mt][kt][3] = a.w;
        }

    const int g  = lane >> 2;
    const int cq = lane & 3;
    const int q  = g & 3;
    const int gh = lane >> 4;

    // bias (used in phase A): gate q, units per slot s
    float bias[4];
#pragma unroll
    for (int s = 0; s < 4; s++) {
        int u_s = wid * 8 + (s >> 1) * 4 + (s & 1) * 2 + gh;
        bias[s] = bih[q * 128 + u_s] + bhh[q * 128 + u_s];
    }

    // non-trans B reader lane addressing (h and x tiles)
    const int n_l = (lane & 7) | ((lane >> 4) << 3);
    const int c16 = (lane >> 3) & 1;
    const uint32_t rbh_lane = (uint32_t)(n_l * 256);   // h tile: 256B rows
    const uint32_t rbx_lane = (uint32_t)(n_l * 128);   // x tile: 128B rows

    // cell ownership + h writeback addresses ([r][u] swizzled layout)
    const int mt_c = q >> 1, rh_c = q & 1;
    const int u_c  = wid * 8 + mt_c * 4 + rh_c * 2 + gh;
    const int cw   = u_c >> 3;
    const int uo   = (u_c & 7) * 2;
    uint32_t h_wr4[2][2];
#pragma unroll
    for (int nt = 0; nt < 2; nt++)
#pragma unroll
        for (int ci = 0; ci < 2; ci++) {
            int r = nt * 8 + cq * 2 + ci;
            h_wr4[nt][ci] = (uint32_t)(HB_OFF + r * 256
                            + ((cw ^ (r & 7)) << 4) + uo);
        }

    // activation constants (lane's gate q): sigmoid = 0.5*tanh(0.5x)+0.5
    const float sc = (q == 2) ? 1.0f : 0.5f;
    const __half2 A2 = __float2half2_rn(q == 2 ? 1.0f : 0.5f);
    const __half2 B2 = __float2half2_rn(q == 2 ? 0.0f : 0.5f);

    // x staging: thread covers row sw, f-pair 2*sl, 8 tl per chunk
    const int sl = tid & 31, sw = tid >> 5;
    const float* xrow = x + ((size_t)(b0 + sw) * T_STEPS) * 64 + 2 * sl;
    const uint32_t xw_off = (uint32_t)(XB_OFF + sw * 128
        + ((((2 * sl) >> 3) ^ (sw & 7)) << 4) + ((2 * sl) & 7) * 2);

    float cs[4];
#pragma unroll
    for (int i = 0; i < 4; i++) cs[i] = 0.0f;

    // prologue: load x chunk 0
    float2 fr[8];
#pragma unroll
    for (int tt = 0; tt < 8; tt++) fr[tt] = *(const float2*)(xrow + tt * 64);

    const int p0 = q & 1, p1 = q >> 1;

    for (int c = 0; c < 32; c++) {
        // ---- stage x chunk c; prefetch chunk c+1 ----
#pragma unroll
        for (int tt = 0; tt < 8; tt++)
            *(uint32_t*)(smem + xw_off + tt * 2048) = f2h2(fr[tt].x, fr[tt].y);
        if (c + 1 < 32) {
#pragma unroll
            for (int tt = 0; tt < 8; tt++)
                fr[tt] = *(const float2*)(xrow + ((c + 1) * 8 + tt) * 64);
        }
        __syncthreads();                  // x chunk c visible (gx buf free: c-1 consumed)

        // ---- phase A: gx[tl] = bias + W_ih x_{8c+tl}, into smem ----
        {
            uint32_t ax[2][4][4];
#pragma unroll
            for (int mt = 0; mt < 2; mt++)
#pragma unroll
                for (int kt = 0; kt < 4; kt++) {
                    uint4 a = g_wih_f[((wid * 2 + mt) * 4 + kt) * 32 + lane];
                    ax[mt][kt][0] = a.x; ax[mt][kt][1] = a.y;
                    ax[mt][kt][2] = a.z; ax[mt][kt][3] = a.w;
                }
#pragma unroll 1
            for (int tl = 0; tl < 8; tl++) {
                float Dx[2][8];
#pragma unroll
                for (int mt = 0; mt < 2; mt++)
#pragma unroll
                    for (int nt = 0; nt < 2; nt++) {
                        Dx[mt][nt * 4 + 0] = bias[mt * 2];     Dx[mt][nt * 4 + 1] = bias[mt * 2];
                        Dx[mt][nt * 4 + 2] = bias[mt * 2 + 1]; Dx[mt][nt * 4 + 3] = bias[mt * 2 + 1];
                    }
#pragma unroll
                for (int kt = 0; kt < 4; kt++) {
                    uint32_t v0, v1, v2, v3;
                    uint32_t addr = sb + XB_OFF + rbx_lane + (uint32_t)(tl * 2048)
                        + (uint32_t)((((kt * 2 + c16) ^ (n_l & 7)) << 4));
                    LDSM_X4(v0, v1, v2, v3, addr);
#pragma unroll
                    for (int mt = 0; mt < 2; mt++) {
                        MMA16816(&Dx[mt][0], ax[mt][kt][0], ax[mt][kt][1],
                                 ax[mt][kt][2], ax[mt][kt][3], v0, v1);
                        MMA16816(&Dx[mt][4], ax[mt][kt][0], ax[mt][kt][1],
                                 ax[mt][kt][2], ax[mt][kt][3], v2, v3);
                    }
                }
                uint32_t u[8];
#pragma unroll
                for (int mt = 0; mt < 2; mt++)
#pragma unroll
                    for (int nt = 0; nt < 2; nt++)
#pragma unroll
                        for (int rh = 0; rh < 2; rh++)
                            u[mt * 4 + nt * 2 + rh] =
                                f2h2(Dx[mt][nt * 4 + rh * 2], Dx[mt][nt * 4 + rh * 2 + 1]);
                *(uint4*)(smem + GX_OFF + tl * 16384 + tid * 16) =
                    make_uint4(u[0], u[1], u[2], u[3]);
                *(uint4*)(smem + GX_OFF + tl * 16384 + 8192 + tid * 16) =
                    make_uint4(u[4], u[5], u[6], u[7]);
            }
        }
        __syncthreads();                  // x chunk c reads done (tile reusable)

        // ---- 8 recurrence steps ----
#pragma unroll 1
        for (int tl = 0; tl < 8; tl++) {
            const int t = c * 8 + tl;
            const uint32_t cur = (uint32_t)(tl & 1);
            const uint32_t hb_cur = sb + HB_OFF + cur * 4096 + rbh_lane;

            // D init from same-thread gx (no sync needed)
            uint4 gA = *(const uint4*)(smem + GX_OFF + tl * 16384 + tid * 16);
            uint4 gB = *(const uint4*)(smem + GX_OFF + tl * 16384 + 8192 + tid * 16);
            float D[2][8];
            {
                uint32_t uu[8] = {gA.x, gA.y, gA.z, gA.w, gB.x, gB.y, gB.z, gB.w};
#pragma unroll
                for (int mt = 0; mt < 2; mt++)
#pragma unroll
                    for (int nt = 0; nt < 2; nt++)
#pragma unroll
                        for (int rh = 0; rh < 2; rh++) {
                            float2 f = __half22float2(*(__half2*)&uu[mt * 4 + nt * 2 + rh]);
                            D[mt][nt * 4 + rh * 2]     = f.x;
                            D[mt][nt * 4 + rh * 2 + 1] = f.y;
                        }
            }

            // h-GEMM: D += W_hh h_{t-1}; B via non-trans ldmatrix
#pragma unroll
            for (int kt = 0; kt < 8; kt++) {
                uint32_t v0, v1, v2, v3;
                uint32_t addr = hb_cur + (uint32_t)((((kt * 2 + c16) ^ (n_l & 7)) << 4));
                LDSM_X4(v0, v1, v2, v3, addr);
#pragma unroll
                for (int mt = 0; mt < 2; mt++) {
                    MMA16816(&D[mt][0], ah[mt][kt][0], ah[mt][kt][1],
                             ah[mt][kt][2], ah[mt][kt][3], v0, v1);
                    MMA16816(&D[mt][4], ah[mt][kt][0], ah[mt][kt][1],
                             ah[mt][kt][2], ah[mt][kt][3], v2, v3);
                }
            }

            // f16x2 activations (lane's gate q)
            uint32_t sv[4][2];
#pragma unroll
            for (int mt = 0; mt < 2; mt++)
#pragma unroll
                for (int rh = 0; rh < 2; rh++)
#pragma unroll
                    for (int nt = 0; nt < 2; nt++) {
                        uint32_t hp = f2h2(D[mt][nt * 4 + rh * 2] * sc,
                                           D[mt][nt * 4 + rh * 2 + 1] * sc);
                        uint32_t th = tanh2(hp);
                        __half2 act = __hfma2(*(__half2*)&th, A2, B2);
                        sv[mt * 2 + rh][nt] = *(uint32_t*)&act;
                    }

            // packed 4x4 butterfly transpose (gates -> cell owner)
#pragma unroll
            for (int s1 = 0; s1 < 2; s1++)
#pragma unroll
                for (int nt = 0; nt < 2; nt++) {
                    uint32_t a0 = sv[s1 * 2][nt], a1 = sv[s1 * 2 + 1][nt];
                    uint32_t send = p0 ? a0 : a1;
                    uint32_t got = __shfl_xor_sync(0xFFFFFFFFu, send, 4);
                    sv[s1 * 2][nt]     = p0 ? got : a0;
                    sv[s1 * 2 + 1][nt] = p0 ? a1 : got;
                }
#pragma unroll
            for (int s0 = 0; s0 < 2; s0++)
#pragma unroll
                for (int nt = 0; nt < 2; nt++) {
                    uint32_t a0 = sv[s0][nt], a1 = sv[2 + s0][nt];
                    uint32_t send = p1 ? a0 : a1;
                    uint32_t got = __shfl_xor_sync(0xFFFFFFFFu, send, 8);
                    sv[s0][nt]     = p1 ? got : a0;
                    sv[2 + s0][nt] = p1 ? a1 : got;
                }

            // cell update + h writeback
            const uint32_t nxt = (cur ^ 1u) * 4096u;
#pragma unroll
            for (int nt = 0; nt < 2; nt++) {
                float2 fi = __half22float2(*(__half2*)&sv[0][nt]);
                float2 ff = __half22float2(*(__half2*)&sv[1][nt]);
                float2 fg = __half22float2(*(__half2*)&sv[2][nt]);
                cs[nt * 2 + 0] = ff.x * cs[nt * 2 + 0] + fi.x * fg.x;
                cs[nt * 2 + 1] = ff.y * cs[nt * 2 + 1] + fi.y * fg.y;
                uint32_t cp = f2h2(cs[nt * 2], cs[nt * 2 + 1]);
                uint32_t tc = tanh2(cp);
                __half2 h2v = __hmul2(*(__half2*)&tc, *(__half2*)&sv[3][nt]);
                *(__half*)(smem + h_wr4[nt][0] + nxt) = __low2half(h2v);
                *(__half*)(smem + h_wr4[nt][1] + nxt) = __high2half(h2v);
                if (t == T_STEPS - 1) {
                    float2 hf = __half22float2(h2v);
                    int r = nt * 8 + cq * 2;
                    *(float*)(smem + HS_OFF + (u_c * 16 + r) * 4)     = hf.x;
                    *(float*)(smem + HS_OFF + (u_c * 16 + r + 1) * 4) = hf.y;
                }
            }

            __syncthreads();              // h_t visible; h reads of step t done
        }
    }

    // ---- head: Linear(128,32) -> ReLU -> Linear(32,1) -> Sigmoid ----
    float* W1t = (float*)(smem + W1T_OFF);
    float* zS  = (float*)(smem + ZS_OFF);
    const float* hs = (const float*)(smem + HS_OFF);
    for (int i = tid; i < 32 * 128; i += NTHREADS) {
        int m = i >> 7, k = i & 127;
        W1t[k * 32 + m] = W1[i];
    }
    __syncthreads();
    {
        int m = tid & 31, r = (tid >> 5) & 15;
        float z = b1[m];
        for (int k = 0; k < 128; k++)
            z += hs[k * 16 + r] * W1t[k * 32 + m];
        zS[r * 32 + m] = fmaxf(z, 0.0f);
    }
    __syncthreads();
    if (tid < 16) {
        float ssum = b2[0];
#pragma unroll
        for (int mm = 0; mm < 32; mm++) ssum += zS[tid * 32 + mm] * W2[mm];
        out[blockIdx.x * 16 + tid] = sigm_exact(ssum);
    }
}

extern "C" void kernel_launch(void* const* d_in, const int* in_sizes, int n_in,
                              void* d_out, int out_size) {
    (void)in_sizes; (void)n_in; (void)out_size;
    const float* x   = (const float*)d_in[0];
    const float* Wih = (const float*)d_in[1];
    const float* Whh = (const float*)d_in[2];
    const float* bih = (const float*)d_in[3];
    const float* bhh = (const float*)d_in[4];
    const float* W1  = (const float*)d_in[5];
    const float* b1  = (const float*)d_in[6];
    const float* W2  = (const float*)d_in[7];
    const float* b2  = (const float*)d_in[8];
    float* out = (float*)d_out;

    cudaFuncSetAttribute(lstm_fused_kernel,
                         cudaFuncAttributeMaxDynamicSharedMemorySize, SMEM_TOTAL);
    prepack_kernel<<<48, 256>>>(Wih, Whh);
    lstm_fused_kernel<<<NBLOCKS, NTHREADS, SMEM_TOTAL>>>(
        x, bih, bhh, W1, b1, W2, b2, out);
}

// round 13
// speedup vs baseline: 1.1599x; 1.1599x over previous
#include <cuda_runtime.h>
#include <cuda_fp16.h>
#include <cstdint>

// LSTMClassifier B=2048,T=256,F=64,H=128 via mma.sync (HMMA) on sm_103.
// K1 prepack: weights fp32 -> fp16 A-frags in global, frag order; rows of
//             gates i,f,o pre-scaled by 0.5 (sigmoid = 0.5*tanh(0.5x)+0.5).
// K2 prepass: gx[t] = 0.5-scaled(W_ih x_t + bias), fp32 accum -> fp16, in the
//             loop's f16-accum D-fragment layout.
// K3 loop:    D(f16x2) = gx[t] (prefetched uint4 = direct D init) + W_hh h.
//             m16n8k16.f16 accumulate; activation = tanh2 + HFMA2 only;
//             packed butterfly; one __syncthreads per step.

#define T_STEPS 256
#define NTHREADS 512
#define NBLOCKS 128

__device__ uint4 g_gx[33554432];      // [128 bblk][256 t][512 tid][2] fp16 gates
__device__ uint4 g_whh_f[8192];       // [32 mt][8 kt][32 lane] A-frags
__device__ uint4 g_wih_f[4096];       // [32 mt][4 kt][32 lane] A-frags

__device__ __forceinline__ uint32_t smem_u32(const void* p) {
    uint32_t a;
    asm("{ .reg .u64 t; cvta.to.shared.u64 t, %1; cvt.u32.u64 %0, t; }" : "=r"(a) : "l"(p));
    return a;
}
__device__ __forceinline__ uint32_t f2h2(float a, float b) {
    __half2 h = __floats2half2_rn(a, b);
    return *(uint32_t*)&h;
}
__device__ __forceinline__ uint32_t tanh2(uint32_t x) {
    uint32_t r;
    asm("tanh.approx.f16x2 %0, %1;" : "=r"(r) : "r"(x));
    return r;
}

#define LDSM_X4(r0, r1, r2, r3, a) \
    asm volatile("ldmatrix.sync.aligned.m8n8.x4.shared.b16 {%0,%1,%2,%3}, [%4];" \
                 : "=r"(r0), "=r"(r1), "=r"(r2), "=r"(r3) : "r"(a))

#define MMA16816(d, a0, a1, a2, a3, b0, b1) \
    asm volatile("mma.sync.aligned.m16n8k16.row.col.f32.f16.f16.f32 " \
                 "{%0,%1,%2,%3}, {%4,%5,%6,%7}, {%8,%9}, {%0,%1,%2,%3};" \
                 : "+f"((d)[0]), "+f"((d)[1]), "+f"((d)[2]), "+f"((d)[3]) \
                 : "r"(a0), "r"(a1), "r"(a2), "r"(a3), "r"(b0), "r"(b1))

#define MMA16816_H(d0, d1, a0, a1, a2, a3, b0, b1) \
    asm volatile("mma.sync.aligned.m16n8k16.row.col.f16.f16.f16.f16 " \
                 "{%0,%1}, {%2,%3,%4,%5}, {%6,%7}, {%0,%1};" \
                 : "+r"(d0), "+r"(d1) \
                 : "r"(a0), "r"(a1), "r"(a2), "r"(a3), "r"(b0), "r"(b1))

__device__ __forceinline__ float sigm_exact(float v) {
    float e = __expf(-v);
    return __fdividef(1.0f, 1.0f + e);
}

// ===================== K1: prepack weights into fragment order ==============
// Rows of gates q != 2 (i, f, o) scaled by 0.5 (sigmoid-from-tanh folding).
__global__ void prepack_kernel(const float* __restrict__ Wih,
                               const float* __restrict__ Whh) {
    int idx = blockIdx.x * blockDim.x + threadIdx.x;   // 0..12287
    int isIh = idx >= 8192;
    int id = isIh ? idx - 8192 : idx;
    int lane = id & 31;
    int ktc = isIh ? 4 : 8;
    int kt = (id >> 5) % ktc;
    int mt = (id >> 5) / ktc;
    if (mt >= 32) return;
    int g = lane >> 2, cq = lane & 3;
    uint32_t u[4];
#pragma unroll
    for (int i = 0; i < 4; i++) {
        int j  = g + (i & 1) * 8;
        int kl = 2 * cq + (i >> 1) * 8;
        int pr = mt * 16 + j;
        int uu = pr >> 2, q = pr & 3;
        int row = q * 128 + uu;
        float sc = (q == 2) ? 1.0f : 0.5f;
        float2 v;
        if (isIh) v = *(const float2*)(Wih + row * 64 + kt * 16 + kl);
        else      v = *(const float2*)(Whh + row * 128 + kt * 16 + kl);
        u[i] = f2h2(v.x * sc, v.y * sc);
    }
    uint4 val = make_uint4(u[0], u[1], u[2], u[3]);
    if (isIh) g_wih_f[(mt * 4 + kt) * 32 + lane] = val;
    else      g_whh_f[(mt * 8 + kt) * 32 + lane] = val;
}

// ===================== K2: prepass gx = scaled(W_ih x + bias) ===============
#define PRE_SMEM 32768

__global__ __launch_bounds__(NTHREADS, 1) void prepass_kernel(
    const float* __restrict__ x,
    const float* __restrict__ bih, const float* __restrict__ bhh)
{
    extern __shared__ char smem[];
    const uint32_t sb = smem_u32(smem);
    const int tid  = threadIdx.x;
    const int wid  = tid >> 5;
    const int lane = tid & 31;
    const int b0   = blockIdx.x * 16;

    uint32_t ax[2][4][4];
#pragma unroll
    for (int mt = 0; mt < 2; mt++)
#pragma unroll
        for (int kt = 0; kt < 4; kt++) {
            uint4 a = g_wih_f[((wid * 2 + mt) * 4 + kt) * 32 + lane];
            ax[mt][kt][0] = a.x; ax[mt][kt][1] = a.y;
            ax[mt][kt][2] = a.z; ax[mt][kt][3] = a.w;
        }

    const int g  = lane >> 2;
    const int q  = g & 3;
    const int gh = lane >> 4;
    const float bsc = (q == 2) ? 1.0f : 0.5f;   // bias scaled to match weights
    float bias[4];
#pragma unroll
    for (int s = 0; s < 4; s++) {
        int u_s = wid * 8 + (s >> 1) * 4 + (s & 1) * 2 + gh;
        bias[s] = (bih[q * 128 + u_s] + bhh[q * 128 + u_s]) * bsc;
    }

    const int sl = tid & 31, sw = tid >> 5;
    const float* xrow = x + ((size_t)(b0 + sw) * T_STEPS) * 64 + 2 * sl;
    const uint32_t w_off = (uint32_t)(sw * 128
        + ((((2 * sl) >> 3) ^ (sw & 7)) << 4) + ((2 * sl) & 7) * 2);

    const int n_l = (lane & 7) | ((lane >> 4) << 3);
    const int c16 = (lane >> 3) & 1;
    const uint32_t r_base = sb + (uint32_t)(n_l * 128);

    float2 fr[8];
#pragma unroll
    for (int tt = 0; tt < 8; tt++) fr[tt] = *(const float2*)(xrow + tt * 64);
#pragma unroll
    for (int tt = 0; tt < 8; tt++)
        *(uint32_t*)(smem + tt * 2048 + w_off) = f2h2(fr[tt].x, fr[tt].y);

    for (int c = 0; c < 32; c++) {
        const uint32_t rbuf = (uint32_t)(c & 1) * 16384u;
        const uint32_t wbuf = rbuf ^ 16384u;
        __syncthreads();

        if (c + 1 < 32) {
#pragma unroll
            for (int tt = 0; tt < 8; tt++)
                fr[tt] = *(const float2*)(xrow + ((c + 1) * 8 + tt) * 64);
        }

#pragma unroll 1
        for (int tl = 0; tl < 8; tl++) {
            const int tglob = c * 8 + tl;
            float D[2][8];
#pragma unroll
            for (int mt = 0; mt < 2; mt++)
#pragma unroll
                for (int nt = 0; nt < 2; nt++) {
                    D[mt][nt * 4 + 0] = bias[mt * 2];     D[mt][nt * 4 + 1] = bias[mt * 2];
                    D[mt][nt * 4 + 2] = bias[mt * 2 + 1]; D[mt][nt * 4 + 3] = bias[mt * 2 + 1];
                }
#pragma unroll
            for (int kt = 0; kt < 4; kt++) {
                uint32_t v0, v1, v2, v3;
                uint32_t addr = r_base + rbuf + (uint32_t)(tl * 2048)
                    + (uint32_t)((((kt * 2 + c16) ^ (n_l & 7)) << 4));
                LDSM_X4(v0, v1, v2, v3, addr);
#pragma unroll
                for (int mt = 0; mt < 2; mt++) {
                    MMA16816(&D[mt][0], ax[mt][kt][0], ax[mt][kt][1],
                             ax[mt][kt][2], ax[mt][kt][3], v0, v1);
                    MMA16816(&D[mt][4], ax[mt][kt][0], ax[mt][kt][1],
                             ax[mt][kt][2], ax[mt][kt][3], v2, v3);
                }
            }
            uint32_t u[8];
#pragma unroll
            for (int mt = 0; mt < 2; mt++)
#pragma unroll
                for (int nt = 0; nt < 2; nt++)
#pragma unroll
                    for (int rh = 0; rh < 2; rh++)
                        u[mt * 4 + nt * 2 + rh] =
                            f2h2(D[mt][nt * 4 + rh * 2], D[mt][nt * 4 + rh * 2 + 1]);
            uint4* gp = g_gx + ((size_t)(blockIdx.x * T_STEPS + tglob) * NTHREADS + tid) * 2;
            gp[0] = make_uint4(u[0], u[1], u[2], u[3]);
            gp[1] = make_uint4(u[4], u[5], u[6], u[7]);
        }

        if (c + 1 < 32) {
#pragma unroll
            for (int tt = 0; tt < 8; tt++)
                *(uint32_t*)(smem + wbuf + tt * 2048 + w_off) = f2h2(fr[tt].x, fr[tt].y);
        }
    }
}

// ===================== K3: recurrent loop (f16 accumulators) ================
// h tile per buffer: [16 r][128 u] fp16 = 16 x 256B; chunk swizzle c ^ (r&7).
// smem: W1t 16KB | h dbuf 2x4KB | final h fp32 8KB | zS 2KB
#define W1T_OFF 0
#define HB_OFF  16384
#define HS_OFF  (HB_OFF + 8192)
#define ZS_OFF  (HS_OFF + 8192)
#define SMEM_TOTAL (ZS_OFF + 2048)

__global__ __launch_bounds__(NTHREADS, 1) void lstm_mma_kernel(
    const float* __restrict__ W1, const float* __restrict__ b1,
    const float* __restrict__ W2, const float* __restrict__ b2,
    float* __restrict__ out)
{
    extern __shared__ char smem[];
    const uint32_t sb = smem_u32(smem);
    const int tid  = threadIdx.x;
    const int wid  = tid >> 5;
    const int lane = tid & 31;

    // zero h buffer 0 (h0 = 0)
    for (int i = tid; i < 1024; i += NTHREADS)
        ((uint32_t*)(smem + HB_OFF))[i] = 0;

    // W_hh A-frags from prepacked global
    uint32_t ah[2][8][4];
#pragma unroll
    for (int mt = 0; mt < 2; mt++)
#pragma unroll
        for (int kt = 0; kt < 8; kt++) {
            uint4 a = g_whh_f[((wid * 2 + mt) * 8 + kt) * 32 + lane];
            ah[mt][kt][0] = a.x; ah[mt][kt][1] = a.y;
            ah[mt][kt][2] = a.z; ah[mt][kt][3] = a.w;
        }

    const int g  = lane >> 2;
    const int cq = lane & 3;
    const int q  = g & 3;
    const int gh = lane >> 4;

    // non-trans B reader lane addressing
    const int n_l = (lane & 7) | ((lane >> 4) << 3);
    const int c16 = (lane >> 3) & 1;
    const uint32_t rb_lane = (uint32_t)(n_l * 256);

    // cell ownership + h writeback addresses ([r][u] swizzled layout)
    const int mt_c = q >> 1, rh_c = q & 1;
    const int u_c  = wid * 8 + mt_c * 4 + rh_c * 2 + gh;
    const int cw   = u_c >> 3;
    const int uo   = (u_c & 7) * 2;
    uint32_t h_wr4[2][2];
#pragma unroll
    for (int nt = 0; nt < 2; nt++)
#pragma unroll
        for (int ci = 0; ci < 2; ci++) {
            int r = nt * 8 + cq * 2 + ci;
            h_wr4[nt][ci] = (uint32_t)(HB_OFF + r * 256
                            + ((cw ^ (r & 7)) << 4) + uo);
        }

    // activation constants: D is pre-scaled; act = tanh2(D)*A2 + B2
    const __half2 A2 = __float2half2_rn(q == 2 ? 1.0f : 0.5f);
    const __half2 B2 = __float2half2_rn(q == 2 ? 0.0f : 0.5f);

    __syncthreads();                      // h0 zeroed

    float cs[4];
#pragma unroll
    for (int i = 0; i < 4; i++) cs[i] = 0.0f;

    const uint4* gxp = g_gx + ((size_t)(blockIdx.x * T_STEPS) * NTHREADS + tid) * 2;
    uint4 gA = gxp[0], gB = gxp[1];       // t = 0

    // D as f16x2: Dh[mt][nt][rh]; init IS the prefetched gx (no unpack)
    uint32_t Dh[2][2][2];
    Dh[0][0][0] = gA.x; Dh[0][0][1] = gA.y; Dh[0][1][0] = gA.z; Dh[0][1][1] = gA.w;
    Dh[1][0][0] = gB.x; Dh[1][0][1] = gB.y; Dh[1][1][0] = gB.z; Dh[1][1][1] = gB.w;
    gA = gxp[1024]; gB = gxp[1025];       // t = 1

    const int p0 = q & 1, p1 = q >> 1;

    for (int t = 0; t < T_STEPS; t++) {
        const uint32_t cur = (uint32_t)(t & 1);
        const uint32_t hb_cur = sb + HB_OFF + cur * 4096 + rb_lane;

        // ---- h-GEMM: D += scaled(W_hh) h_{t-1}; f16 accumulate ----
#pragma unroll
        for (int kt = 0; kt < 8; kt++) {
            uint32_t v0, v1, v2, v3;
            uint32_t addr = hb_cur + (uint32_t)((((kt * 2 + c16) ^ (n_l & 7)) << 4));
            LDSM_X4(v0, v1, v2, v3, addr);
#pragma unroll
            for (int mt = 0; mt < 2; mt++) {
                MMA16816_H(Dh[mt][0][0], Dh[mt][0][1],
                           ah[mt][kt][0], ah[mt][kt][1], ah[mt][kt][2], ah[mt][kt][3],
                           v0, v1);
                MMA16816_H(Dh[mt][1][0], Dh[mt][1][1],
                           ah[mt][kt][0], ah[mt][kt][1], ah[mt][kt][2], ah[mt][kt][3],
                           v2, v3);
            }
        }

        // ---- activations: tanh2 + HFMA2 only (D pre-scaled) ----
        uint32_t sv[4][2];
#pragma unroll
        for (int mt = 0; mt < 2; mt++)
#pragma unroll
            for (int rh = 0; rh < 2; rh++)
#pragma unroll
                for (int nt = 0; nt < 2; nt++) {
                    uint32_t th = tanh2(Dh[mt][nt][rh]);
                    __half2 act = __hfma2(*(__half2*)&th, A2, B2);
                    sv[mt * 2 + rh][nt] = *(uint32_t*)&act;
                }

        // ---- packed 4x4 butterfly transpose (gates -> cell owner) ----
#pragma unroll
        for (int s1 = 0; s1 < 2; s1++)
#pragma unroll
            for (int nt = 0; nt < 2; nt++) {
                uint32_t a0 = sv[s1 * 2][nt], a1 = sv[s1 * 2 + 1][nt];
                uint32_t send = p0 ? a0 : a1;
                uint32_t got = __shfl_xor_sync(0xFFFFFFFFu, send, 4);
                sv[s1 * 2][nt]     = p0 ? got : a0;
                sv[s1 * 2 + 1][nt] = p0 ? a1 : got;
            }
#pragma unroll
        for (int s0 = 0; s0 < 2; s0++)
#pragma unroll
            for (int nt = 0; nt < 2; nt++) {
                uint32_t a0 = sv[s0][nt], a1 = sv[2 + s0][nt];
                uint32_t send = p1 ? a0 : a1;
                uint32_t got = __shfl_xor_sync(0xFFFFFFFFu, send, 8);
                sv[s0][nt]     = p1 ? got : a0;
                sv[2 + s0][nt] = p1 ? a1 : got;
            }
        // sv[gate][nt]: half2 = cells (ci=0, ci=1)

        // ---- cell update (fp32 c-state) + h writeback ----
        const uint32_t nxt = (cur ^ 1u) * 4096u;
#pragma unroll
        for (int nt = 0; nt < 2; nt++) {
            float2 fi = __half22float2(*(__half2*)&sv[0][nt]);
            float2 ff = __half22float2(*(__half2*)&sv[1][nt]);
            float2 fg = __half22float2(*(__half2*)&sv[2][nt]);
            cs[nt * 2 + 0] = ff.x * cs[nt * 2 + 0] + fi.x * fg.x;
            cs[nt * 2 + 1] = ff.y * cs[nt * 2 + 1] + fi.y * fg.y;
            uint32_t cp = f2h2(cs[nt * 2], cs[nt * 2 + 1]);
            uint32_t tc = tanh2(cp);
            __half2 h2v = __hmul2(*(__half2*)&tc, *(__half2*)&sv[3][nt]);
            *(__half*)(smem + h_wr4[nt][0] + nxt) = __low2half(h2v);
            *(__half*)(smem + h_wr4[nt][1] + nxt) = __high2half(h2v);
            if (t == T_STEPS - 1) {
                float2 hf = __half22float2(h2v);
                int r = nt * 8 + cq * 2;
                *(float*)(smem + HS_OFF + (u_c * 16 + r) * 4)     = hf.x;
                *(float*)(smem + HS_OFF + (u_c * 16 + r + 1) * 4) = hf.y;
            }
        }

        // ---- D init for t+1 from prefetched gx; issue loads for t+2 ----
        Dh[0][0][0] = gA.x; Dh[0][0][1] = gA.y; Dh[0][1][0] = gA.z; Dh[0][1][1] = gA.w;
        Dh[1][0][0] = gB.x; Dh[1][0][1] = gB.y; Dh[1][1][0] = gB.z; Dh[1][1][1] = gB.w;
        {
            int tt = t + 2; if (tt > T_STEPS - 1) tt = T_STEPS - 1;
            gA = gxp[(size_t)tt * 1024];
            gB = gxp[(size_t)tt * 1024 + 1];
        }

        __syncthreads();                  // h_t visible; h reads of t done
    }

    // ---- head: Linear(128,32) -> ReLU -> Linear(32,1) -> Sigmoid ----
    float* W1t = (float*)(smem + W1T_OFF);
    float* zS  = (float*)(smem + ZS_OFF);
    const float* hs = (const float*)(smem + HS_OFF);
    for (int i = tid; i < 32 * 128; i += NTHREADS) {
        int m = i >> 7, k = i & 127;
        W1t[k * 32 + m] = W1[i];
    }
    __syncthreads();
    {
        int m = tid & 31, r = (tid >> 5) & 15;
        float z = b1[m];
        for (int k = 0; k < 128; k++)
            z += hs[k * 16 + r] * W1t[k * 32 + m];
        zS[r * 32 + m] = fmaxf(z, 0.0f);
    }
    __syncthreads();
    if (tid < 16) {
        float ssum = b2[0];
#pragma unroll
        for (int mm = 0; mm < 32; mm++) ssum += zS[tid * 32 + mm] * W2[mm];
        out[blockIdx.x * 16 + tid] = sigm_exact(ssum);
    }
}

extern "C" void kernel_launch(void* const* d_in, const int* in_sizes, int n_in,
                              void* d_out, int out_size) {
    (void)in_sizes; (void)n_in; (void)out_size;
    const float* x   = (const float*)d_in[0];
    const float* Wih = (const float*)d_in[1];
    const float* Whh = (const float*)d_in[2];
    const float* bih = (const float*)d_in[3];
    const float* bhh = (const float*)d_in[4];
    const float* W1  = (const float*)d_in[5];
    const float* b1  = (const float*)d_in[6];
    const float* W2  = (const float*)d_in[7];
    const float* b2  = (const float*)d_in[8];
    float* out = (float*)d_out;

    cudaFuncSetAttribute(prepass_kernel,
                         cudaFuncAttributeMaxDynamicSharedMemorySize, PRE_SMEM);
    cudaFuncSetAttribute(lstm_mma_kernel,
                         cudaFuncAttributeMaxDynamicSharedMemorySize, SMEM_TOTAL);
    prepack_kernel<<<48, 256>>>(Wih, Whh);
    prepass_kernel<<<NBLOCKS, NTHREADS, PRE_SMEM>>>(x, bih, bhh);
    lstm_mma_kernel<<<NBLOCKS, NTHREADS, SMEM_TOTAL>>>(W1, b1, W2, b2, out);
}